// round 10
// baseline (speedup 1.0000x reference)
#include <cuda_runtime.h>

#define N   512
#define DIM 384
typedef unsigned long long ull;

// Scratch (device globals per allocation-free rule)
__device__ float    g_prec[N];     // per-query soft precision
__device__ unsigned g_ctr;         // monotonic ticket (replay-safe)

__device__ __forceinline__ float sigmoid_nb(float x) {
    float e = __expf(-fabsf(x));
    float p = __fdividef(1.f, 1.f + e);
    return (x >= 0.f) ? p : 1.f - p;
}
__device__ __forceinline__ void fma2(ull& d, ull a, ull b) {
    asm("fma.rn.f32x2 %0, %1, %2, %0;" : "+l"(d) : "l"(a), "l"(b));
}
__device__ __forceinline__ float hadd2(ull v) {
    float2 r;
    asm("mov.b64 {%0, %1}, %2;" : "=f"(r.x), "=f"(r.y) : "l"(v));
    return r.x + r.y;
}

// One kernel: block b owns queries 4b..4b+3. Streams all gallery rows from L2,
// builds the 4 distance rows in smem, then computes soft precision block-locally.
__global__ void __launch_bounds__(512, 1)
k_all(const float* __restrict__ emb, const int* __restrict__ labels,
      float* __restrict__ out)
{
    __shared__ __align__(16) float sq[4][DIM];   // 4 query rows
    __shared__ __align__(16) float sd[4][N];     // 4 distance rows
    __shared__ int   slab[N];
    __shared__ float sqn[4];
    __shared__ float wnum[16];
    __shared__ int   wcnt[16];
    __shared__ float swr[16];
    __shared__ int   s_done;

    const int t    = threadIdx.x;
    const int lane = t & 31;
    const int w    = t >> 5;          // 16 warps
    const int qb   = blockIdx.x * 4;

    // ---------- prologue: queries + labels to smem ----------
    if (t < 384) ((float4*)sq)[t] = ((const float4*)(emb + (size_t)qb * DIM))[t];
    if (t < 128) ((int4*)slab)[t] = ((const int4*)labels)[t];
    __syncthreads();

    // q norms: warp w (<4) reduces q-row w
    if (w < 4) {
        const ulonglong2* qp = (const ulonglong2*)sq[w];
        ull an = 0;
#pragma unroll
        for (int c = 0; c < 3; c++) {
            ulonglong2 v = qp[lane + 32 * c];
            fma2(an, v.x, v.x);
            fma2(an, v.y, v.y);
        }
        float nn = hadd2(an);
#pragma unroll
        for (int o = 16; o; o >>= 1) nn += __shfl_xor_sync(0xffffffffu, nn, o);
        if (lane == 0) sqn[w] = nn;
    }
    __syncthreads();

    // ---------- phase 1: stream gallery, compute distances ----------
    // 8-lane groups: group g of a warp owns 2 rows per pass; lane covers
    // k-slice f = sub + 8j. Each LDG.128 warp-instr touches 4 lines (coalesced).
    const int g   = lane >> 3;
    const int sub = lane & 7;

#pragma unroll 1
    for (int p = 0; p < 4; p++) {
        const int r0 = p * 128 + w * 8 + g * 2;
        const int r1 = r0 + 1;
        const ulonglong2* p0 = (const ulonglong2*)(emb + (size_t)r0 * DIM);
        const ulonglong2* p1 = (const ulonglong2*)(emb + (size_t)r1 * DIM);

        ull aq0[4] = {0,0,0,0}, aq1[4] = {0,0,0,0};
        ull an0 = 0, an1 = 0;
#pragma unroll
        for (int j = 0; j < 12; j++) {
            const int f = sub + 8 * j;
            ulonglong2 u0 = p0[f];
            ulonglong2 u1 = p1[f];
            fma2(an0, u0.x, u0.x); fma2(an0, u0.y, u0.y);
            fma2(an1, u1.x, u1.x); fma2(an1, u1.y, u1.y);
#pragma unroll
            for (int qi = 0; qi < 4; qi++) {
                ulonglong2 qv = ((const ulonglong2*)sq[qi])[f];
                fma2(aq0[qi], u0.x, qv.x); fma2(aq0[qi], u0.y, qv.y);
                fma2(aq1[qi], u1.x, qv.x); fma2(aq1[qi], u1.y, qv.y);
            }
        }

        float n0 = hadd2(an0), n1 = hadd2(an1);
        float d0[4], d1[4];
#pragma unroll
        for (int qi = 0; qi < 4; qi++) { d0[qi] = hadd2(aq0[qi]); d1[qi] = hadd2(aq1[qi]); }
        // reduce across the 8-lane group (xor 1,2,4 stays in-group)
#pragma unroll
        for (int o = 1; o < 8; o <<= 1) {
            n0 += __shfl_xor_sync(0xffffffffu, n0, o);
            n1 += __shfl_xor_sync(0xffffffffu, n1, o);
#pragma unroll
            for (int qi = 0; qi < 4; qi++) {
                d0[qi] += __shfl_xor_sync(0xffffffffu, d0[qi], o);
                d1[qi] += __shfl_xor_sync(0xffffffffu, d1[qi], o);
            }
        }
        if (sub == 0) {
#pragma unroll
            for (int qi = 0; qi < 4; qi++) {
                float dd0 = sqn[qi] + n0 - 2.f * d0[qi];
                float dd1 = sqn[qi] + n1 - 2.f * d1[qi];
                sd[qi][r0] = (r0 == qb + qi) ? 1e6f : sqrtf(fmaxf(dd0, 1e-12f));
                sd[qi][r1] = (r1 == qb + qi) ? 1e6f : sqrtf(fmaxf(dd1, 1e-12f));
            }
        }
    }
    __syncthreads();

    // ---------- phase 2: soft precision (R8 core + R9 near-tie) ----------
    {
        const int   qsel = w & 3;
        const int   q    = qb + qsel;
        const int   lq   = slab[q];
        const float* row = sd[qsel];
        const int   jb   = (w >> 2) * 128;   // quarter-range per warp

        float rv[16];
#pragma unroll
        for (int i = 0; i < 16; i++) rv[i] = row[lane + 32 * i];

        float num = 0.f;
        int   cnt = 0;
#pragma unroll
        for (int c = 0; c < 4; c++) {
            int j = jb + c * 32 + lane;
            bool f = (j != q) && (slab[j] == lq);
            unsigned bm = __ballot_sync(0xffffffffu, f);
            cnt += __popc(bm);
            while (bm) {                     // ascending j: deterministic
                int bit = __ffs(bm) - 1;
                bm &= bm - 1;
                float dj = row[jb + c * 32 + bit];
                float part = 0.f;
#pragma unroll
                for (int i = 0; i < 16; i++) {
                    float x = (dj - rv[i]) * 100.0f;    // 1/T2
                    float stp = (x >= 0.f) ? 1.f : 0.f;
                    part += stp;
                    if (fabsf(x) < 18.f)                // rare near-tie fixup
                        part += sigmoid_nb(x) - stp;
                }
#pragma unroll
                for (int o = 16; o; o >>= 1)
                    part += __shfl_xor_sync(0xffffffffu, part, o);
                num += sigmoid_nb(5.0f - part);         // K=5, T1=1
            }
        }
        if (lane == 0) { wnum[w] = num; wcnt[w] = cnt; }
        __syncthreads();

        if (t < 4) {   // fixed quarter order: deterministic
            float s = wnum[t] + wnum[4 + t] + wnum[8 + t] + wnum[12 + t];
            int   c = wcnt[t] + wcnt[4 + t] + wcnt[8 + t] + wcnt[12 + t];
            g_prec[qb + t] = s / fminf((float)c, 5.0f); // 0/0 -> NaN like reference
        }
    }

    // ---------- tail: last-arriving block does the fixed-order mean ----------
    __syncthreads();
    if (t == 0) {
        __threadfence();
        unsigned tk = atomicAdd(&g_ctr, 1u);
        s_done = ((tk & 127u) == 127u) ? 1 : 0;
    }
    __syncthreads();

    if (s_done) {
        __threadfence();
        float v = __ldcg(&g_prec[t]);        // 512 threads, 512 values
#pragma unroll
        for (int o = 16; o; o >>= 1)
            v += __shfl_xor_sync(0xffffffffu, v, o);
        if (lane == 0) swr[w] = v;
        __syncthreads();
        if (t == 0) {
            float s = 0.f;
#pragma unroll
            for (int i = 0; i < 16; i++) s += swr[i];
            out[0] = 1.0f - s / (float)N;
        }
    }
}

extern "C" void kernel_launch(void* const* d_in, const int* in_sizes, int n_in,
                              void* d_out, int out_size) {
    const float* emb    = (const float*)d_in[0];
    const int*   labels = (const int*)d_in[1];
    k_all<<<128, 512>>>(emb, labels, (float*)d_out);
}

// round 12
// speedup vs baseline: 1.5955x; 1.5955x over previous
#include <cuda_runtime.h>

#define N   512
#define DIM 384
#define BK  32
#define NTL 12          // DIM / BK

// Scratch (device globals per allocation-free rule)
__device__ float    g_D[N * N];    // pairwise distances, diag = 1e6
__device__ float    g_prec[N];     // per-query soft precision
__device__ unsigned g_ctr;         // monotonic ticket (replay-safe)

__device__ __forceinline__ float sigmoid_nb(float x) {
    float e = __expf(-fabsf(x));
    float p = __fdividef(1.f, 1.f + e);
    return (x >= 0.f) ? p : 1.f - p;
}

// ---------------- Kernel 1: Gram -> distance, 4x4 tile, 128 threads ----------------
// Tile 32(q) x 64(m), grid 128. 2 B of LDS per FMA: crossbar and FFMA balanced.
#define SA_STR 36   // 144 B rows: 16B-aligned for LDS.128
#define SB_STR 68   // 272 B rows: 16B-aligned

__global__ void __launch_bounds__(128, 1) k_gram(const float* __restrict__ emb) {
    __shared__ __align__(16) float sa[2][BK * SA_STR];
    __shared__ __align__(16) float sb[2][BK * SB_STR];
    __shared__ float snA[32];
    __shared__ float snB[64];

    const int t  = threadIdx.x;
    const int q0 = (blockIdx.x >> 3) * 32;
    const int m0 = (blockIdx.x & 7) * 64;
    const int ty = t >> 4;       // 0..7  -> 4 q-rows at ty*4
    const int tx = t & 15;       // 0..15 -> 4 m-cols at tx*4

    // A tile 32 rows x 32 k: 256 float4, 2/thread: rows arow, arow+16; k-chunk ac4
    const int arow = t >> 3, ac4 = t & 7;          // arow 0..15, ac4 0..7
    // B tile 64 rows x 32 k: 512 float4, 4/thread: rows arow+16i, k-chunk ac4
    // (same decomposition: row group = t>>3, k-chunk = t&7)

    const float* pa0 = emb + (size_t)(q0 + arow)      * DIM + ac4 * 4;
    const float* pa1 = emb + (size_t)(q0 + arow + 16) * DIM + ac4 * 4;
    const float* pb[4];
#pragma unroll
    for (int i = 0; i < 4; i++)
        pb[i] = emb + (size_t)(m0 + arow + 16 * i) * DIM + ac4 * 4;

    float acc[4][4];
#pragma unroll
    for (int i = 0; i < 4; i++)
#pragma unroll
        for (int j = 0; j < 4; j++) acc[i][j] = 0.f;
    float nA0 = 0.f, nA1 = 0.f;
    float nB[4] = {0.f, 0.f, 0.f, 0.f};

    float4 ra0, ra1, rb[4];
    ra0 = *(const float4*)pa0;
    ra1 = *(const float4*)pa1;
#pragma unroll
    for (int i = 0; i < 4; i++) rb[i] = *(const float4*)pb[i];

    // store tile 0 into buffer 0 (k-major transpose)
#pragma unroll
    for (int e = 0; e < 4; e++) {
        sa[0][(ac4 * 4 + e) * SA_STR + arow]      = ((const float*)&ra0)[e];
        sa[0][(ac4 * 4 + e) * SA_STR + arow + 16] = ((const float*)&ra1)[e];
#pragma unroll
        for (int i = 0; i < 4; i++)
            sb[0][(ac4 * 4 + e) * SB_STR + arow + 16 * i] = ((const float*)&rb[i])[e];
    }
    nA0 = fmaf(ra0.x,ra0.x,fmaf(ra0.y,ra0.y,fmaf(ra0.z,ra0.z,fmaf(ra0.w,ra0.w,nA0))));
    nA1 = fmaf(ra1.x,ra1.x,fmaf(ra1.y,ra1.y,fmaf(ra1.z,ra1.z,fmaf(ra1.w,ra1.w,nA1))));
#pragma unroll
    for (int i = 0; i < 4; i++)
        nB[i] = fmaf(rb[i].x,rb[i].x,fmaf(rb[i].y,rb[i].y,fmaf(rb[i].z,rb[i].z,fmaf(rb[i].w,rb[i].w,nB[i]))));
    __syncthreads();

#pragma unroll 1
    for (int tt = 0; tt < NTL; tt++) {
        const int cur = tt & 1;
        if (tt + 1 < NTL) {   // prefetch next tile into registers
            const int ko = (tt + 1) * BK;
            ra0 = *(const float4*)(pa0 + ko);
            ra1 = *(const float4*)(pa1 + ko);
#pragma unroll
            for (int i = 0; i < 4; i++) rb[i] = *(const float4*)(pb[i] + ko);
        }

#pragma unroll
        for (int k = 0; k < BK; k++) {
            float4 av = *(const float4*)&sa[cur][k * SA_STR + ty * 4];
            float4 bv = *(const float4*)&sb[cur][k * SB_STR + tx * 4];
            acc[0][0] = fmaf(av.x, bv.x, acc[0][0]);
            acc[0][1] = fmaf(av.x, bv.y, acc[0][1]);
            acc[0][2] = fmaf(av.x, bv.z, acc[0][2]);
            acc[0][3] = fmaf(av.x, bv.w, acc[0][3]);
            acc[1][0] = fmaf(av.y, bv.x, acc[1][0]);
            acc[1][1] = fmaf(av.y, bv.y, acc[1][1]);
            acc[1][2] = fmaf(av.y, bv.z, acc[1][2]);
            acc[1][3] = fmaf(av.y, bv.w, acc[1][3]);
            acc[2][0] = fmaf(av.z, bv.x, acc[2][0]);
            acc[2][1] = fmaf(av.z, bv.y, acc[2][1]);
            acc[2][2] = fmaf(av.z, bv.z, acc[2][2]);
            acc[2][3] = fmaf(av.z, bv.w, acc[2][3]);
            acc[3][0] = fmaf(av.w, bv.x, acc[3][0]);
            acc[3][1] = fmaf(av.w, bv.y, acc[3][1]);
            acc[3][2] = fmaf(av.w, bv.z, acc[3][2]);
            acc[3][3] = fmaf(av.w, bv.w, acc[3][3]);
        }

        if (tt + 1 < NTL) {   // store prefetched tile into the other buffer
            const int nxt = cur ^ 1;
#pragma unroll
            for (int e = 0; e < 4; e++) {
                sa[nxt][(ac4 * 4 + e) * SA_STR + arow]      = ((const float*)&ra0)[e];
                sa[nxt][(ac4 * 4 + e) * SA_STR + arow + 16] = ((const float*)&ra1)[e];
#pragma unroll
                for (int i = 0; i < 4; i++)
                    sb[nxt][(ac4 * 4 + e) * SB_STR + arow + 16 * i] = ((const float*)&rb[i])[e];
            }
            nA0 = fmaf(ra0.x,ra0.x,fmaf(ra0.y,ra0.y,fmaf(ra0.z,ra0.z,fmaf(ra0.w,ra0.w,nA0))));
            nA1 = fmaf(ra1.x,ra1.x,fmaf(ra1.y,ra1.y,fmaf(ra1.z,ra1.z,fmaf(ra1.w,ra1.w,nA1))));
#pragma unroll
            for (int i = 0; i < 4; i++)
                nB[i] = fmaf(rb[i].x,rb[i].x,fmaf(rb[i].y,rb[i].y,fmaf(rb[i].z,rb[i].z,fmaf(rb[i].w,rb[i].w,nB[i]))));
            __syncthreads();
        }
    }

    // reduce norms: each row's 8 k-chunk threads share t>>3 -> xor 1,2,4 in-warp
    nA0 += __shfl_xor_sync(0xffffffffu, nA0, 1);
    nA0 += __shfl_xor_sync(0xffffffffu, nA0, 2);
    nA0 += __shfl_xor_sync(0xffffffffu, nA0, 4);
    nA1 += __shfl_xor_sync(0xffffffffu, nA1, 1);
    nA1 += __shfl_xor_sync(0xffffffffu, nA1, 2);
    nA1 += __shfl_xor_sync(0xffffffffu, nA1, 4);
#pragma unroll
    for (int i = 0; i < 4; i++) {
        nB[i] += __shfl_xor_sync(0xffffffffu, nB[i], 1);
        nB[i] += __shfl_xor_sync(0xffffffffu, nB[i], 2);
        nB[i] += __shfl_xor_sync(0xffffffffu, nB[i], 4);
    }
    __syncthreads();
    if (ac4 == 0) {
        snA[arow]      = nA0;
        snA[arow + 16] = nA1;
#pragma unroll
        for (int i = 0; i < 4; i++) snB[arow + 16 * i] = nB[i];
    }
    __syncthreads();

    // epilogue: distances, diag = 1e6
#pragma unroll
    for (int i = 0; i < 4; i++) {
        const int q  = q0 + ty * 4 + i;
        const int mb = m0 + tx * 4;
        const float nq = snA[ty * 4 + i];
        float dv[4];
#pragma unroll
        for (int c = 0; c < 4; c++) {
            float d2 = nq + snB[tx * 4 + c] - 2.f * acc[i][c];
            dv[c] = (q == mb + c) ? 1e6f : sqrtf(fmaxf(d2, 1e-12f));
        }
        *(float4*)&g_D[(size_t)q * N + mb] = make_float4(dv[0], dv[1], dv[2], dv[3]);
    }
}

// ---------------- Kernel 2: soft precision (R8-proven shape + reg-row/near-tie) ----------------
__global__ void __launch_bounds__(512) k_prec(const int* __restrict__ labels,
                                              float* __restrict__ out) {
    __shared__ float sd[4][N];
    __shared__ int   slab[N];
    __shared__ float wnum[16];
    __shared__ int   wcnt[16];
    __shared__ float swr[16];
    __shared__ int   s_done;

    const int t    = threadIdx.x;
    const int lane = t & 31;
    const int w    = t >> 5;
    const int q0   = blockIdx.x * 4;

    ((float4*)sd)[t] = __ldcg(&((const float4*)(g_D + (size_t)q0 * N))[t]);
    if (t < 128) ((int4*)slab)[t] = ((const int4*)labels)[t];
    __syncthreads();

    const int   qsel = w & 3;
    const int   q    = q0 + qsel;
    const int   lq   = slab[q];
    const float* row = sd[qsel];
    const int   jb   = (w >> 2) * 128;

    float rv[16];
#pragma unroll
    for (int i = 0; i < 16; i++) rv[i] = row[lane + 32 * i];

    float num = 0.f;
    int   cnt = 0;
#pragma unroll
    for (int c = 0; c < 4; c++) {
        int j = jb + c * 32 + lane;
        bool f = (j != q) && (slab[j] == lq);
        unsigned bm = __ballot_sync(0xffffffffu, f);
        cnt += __popc(bm);
        while (bm) {                         // ascending j: deterministic
            int bit = __ffs(bm) - 1;
            bm &= bm - 1;
            float dj = row[jb + c * 32 + bit];
            float part = 0.f;
#pragma unroll
            for (int i = 0; i < 16; i++) {
                float x = (dj - rv[i]) * 100.0f;     // 1/T2
                float stp = (x >= 0.f) ? 1.f : 0.f;
                part += stp;
                if (fabsf(x) < 18.f)                 // rare near-tie fixup
                    part += sigmoid_nb(x) - stp;
            }
#pragma unroll
            for (int o = 16; o; o >>= 1)
                part += __shfl_xor_sync(0xffffffffu, part, o);
            num += sigmoid_nb(5.0f - part);          // K=5, T1=1
        }
    }
    if (lane == 0) { wnum[w] = num; wcnt[w] = cnt; }
    __syncthreads();

    if (t < 4) {
        float s = wnum[t] + wnum[4 + t] + wnum[8 + t] + wnum[12 + t];
        int   c = wcnt[t] + wcnt[4 + t] + wcnt[8 + t] + wcnt[12 + t];
        g_prec[q0 + t] = s / fminf((float)c, 5.0f);  // 0/0 -> NaN like reference
    }
    __syncthreads();

    if (t == 0) {
        __threadfence();
        unsigned tk = atomicAdd(&g_ctr, 1u);
        s_done = ((tk & 127u) == 127u) ? 1 : 0;
    }
    __syncthreads();

    if (s_done) {
        __threadfence();
        float v = __ldcg(&g_prec[t]);
#pragma unroll
        for (int o = 16; o; o >>= 1)
            v += __shfl_xor_sync(0xffffffffu, v, o);
        if (lane == 0) swr[w] = v;
        __syncthreads();
        if (t == 0) {
            float s = 0.f;
#pragma unroll
            for (int i = 0; i < 16; i++) s += swr[i];
            out[0] = 1.0f - s / (float)N;
        }
    }
}

extern "C" void kernel_launch(void* const* d_in, const int* in_sizes, int n_in,
                              void* d_out, int out_size) {
    const float* emb    = (const float*)d_in[0];
    const int*   labels = (const int*)d_in[1];
    k_gram<<<128, 128>>>(emb);
    k_prec<<<128, 512>>>(labels, (float*)d_out);
}

// round 13
// speedup vs baseline: 2.0534x; 1.2870x over previous
#include <cuda_runtime.h>

#define N   512
#define DIM 384
#define BK  32
#define NTL 12          // DIM / BK

// Scratch (device globals per allocation-free rule)
__device__ float    g_D[N * N];    // pairwise distances, diag = 1e6
__device__ float    g_prec[N];     // per-query soft precision
__device__ unsigned g_ctr;         // monotonic ticket (replay-safe)

// Branchless full-range sigmoid (exp underflow -> exact 0/1 saturation)
__device__ __forceinline__ float sigmoid_nb(float x) {
    float e = __expf(-fabsf(x));
    float p = __fdividef(1.f, 1.f + e);
    return (x >= 0.f) ? p : 1.f - p;
}

// ---------------- Kernel 1: Gram -> distance, 4x4 tile, 128 threads (R12-proven) ----------------
#define SA_STR 36   // 144 B rows: 16B-aligned for LDS.128
#define SB_STR 68   // 272 B rows: 16B-aligned

__global__ void __launch_bounds__(128, 1) k_gram(const float* __restrict__ emb) {
    __shared__ __align__(16) float sa[2][BK * SA_STR];
    __shared__ __align__(16) float sb[2][BK * SB_STR];
    __shared__ float snA[32];
    __shared__ float snB[64];

    const int t  = threadIdx.x;
    const int q0 = (blockIdx.x >> 3) * 32;
    const int m0 = (blockIdx.x & 7) * 64;
    const int ty = t >> 4;       // 0..7  -> 4 q-rows at ty*4
    const int tx = t & 15;       // 0..15 -> 4 m-cols at tx*4

    const int arow = t >> 3, ac4 = t & 7;          // arow 0..15, ac4 0..7

    const float* pa0 = emb + (size_t)(q0 + arow)      * DIM + ac4 * 4;
    const float* pa1 = emb + (size_t)(q0 + arow + 16) * DIM + ac4 * 4;
    const float* pb[4];
#pragma unroll
    for (int i = 0; i < 4; i++)
        pb[i] = emb + (size_t)(m0 + arow + 16 * i) * DIM + ac4 * 4;

    float acc[4][4];
#pragma unroll
    for (int i = 0; i < 4; i++)
#pragma unroll
        for (int j = 0; j < 4; j++) acc[i][j] = 0.f;
    float nA0 = 0.f, nA1 = 0.f;
    float nB[4] = {0.f, 0.f, 0.f, 0.f};

    float4 ra0, ra1, rb[4];
    ra0 = *(const float4*)pa0;
    ra1 = *(const float4*)pa1;
#pragma unroll
    for (int i = 0; i < 4; i++) rb[i] = *(const float4*)pb[i];

#pragma unroll
    for (int e = 0; e < 4; e++) {
        sa[0][(ac4 * 4 + e) * SA_STR + arow]      = ((const float*)&ra0)[e];
        sa[0][(ac4 * 4 + e) * SA_STR + arow + 16] = ((const float*)&ra1)[e];
#pragma unroll
        for (int i = 0; i < 4; i++)
            sb[0][(ac4 * 4 + e) * SB_STR + arow + 16 * i] = ((const float*)&rb[i])[e];
    }
    nA0 = fmaf(ra0.x,ra0.x,fmaf(ra0.y,ra0.y,fmaf(ra0.z,ra0.z,fmaf(ra0.w,ra0.w,nA0))));
    nA1 = fmaf(ra1.x,ra1.x,fmaf(ra1.y,ra1.y,fmaf(ra1.z,ra1.z,fmaf(ra1.w,ra1.w,nA1))));
#pragma unroll
    for (int i = 0; i < 4; i++)
        nB[i] = fmaf(rb[i].x,rb[i].x,fmaf(rb[i].y,rb[i].y,fmaf(rb[i].z,rb[i].z,fmaf(rb[i].w,rb[i].w,nB[i]))));
    __syncthreads();

#pragma unroll 1
    for (int tt = 0; tt < NTL; tt++) {
        const int cur = tt & 1;
        if (tt + 1 < NTL) {   // prefetch next tile into registers
            const int ko = (tt + 1) * BK;
            ra0 = *(const float4*)(pa0 + ko);
            ra1 = *(const float4*)(pa1 + ko);
#pragma unroll
            for (int i = 0; i < 4; i++) rb[i] = *(const float4*)(pb[i] + ko);
        }

#pragma unroll
        for (int k = 0; k < BK; k++) {
            float4 av = *(const float4*)&sa[cur][k * SA_STR + ty * 4];
            float4 bv = *(const float4*)&sb[cur][k * SB_STR + tx * 4];
            acc[0][0] = fmaf(av.x, bv.x, acc[0][0]);
            acc[0][1] = fmaf(av.x, bv.y, acc[0][1]);
            acc[0][2] = fmaf(av.x, bv.z, acc[0][2]);
            acc[0][3] = fmaf(av.x, bv.w, acc[0][3]);
            acc[1][0] = fmaf(av.y, bv.x, acc[1][0]);
            acc[1][1] = fmaf(av.y, bv.y, acc[1][1]);
            acc[1][2] = fmaf(av.y, bv.z, acc[1][2]);
            acc[1][3] = fmaf(av.y, bv.w, acc[1][3]);
            acc[2][0] = fmaf(av.z, bv.x, acc[2][0]);
            acc[2][1] = fmaf(av.z, bv.y, acc[2][1]);
            acc[2][2] = fmaf(av.z, bv.z, acc[2][2]);
            acc[2][3] = fmaf(av.z, bv.w, acc[2][3]);
            acc[3][0] = fmaf(av.w, bv.x, acc[3][0]);
            acc[3][1] = fmaf(av.w, bv.y, acc[3][1]);
            acc[3][2] = fmaf(av.w, bv.z, acc[3][2]);
            acc[3][3] = fmaf(av.w, bv.w, acc[3][3]);
        }

        if (tt + 1 < NTL) {   // store prefetched tile into the other buffer
            const int nxt = cur ^ 1;
#pragma unroll
            for (int e = 0; e < 4; e++) {
                sa[nxt][(ac4 * 4 + e) * SA_STR + arow]      = ((const float*)&ra0)[e];
                sa[nxt][(ac4 * 4 + e) * SA_STR + arow + 16] = ((const float*)&ra1)[e];
#pragma unroll
                for (int i = 0; i < 4; i++)
                    sb[nxt][(ac4 * 4 + e) * SB_STR + arow + 16 * i] = ((const float*)&rb[i])[e];
            }
            nA0 = fmaf(ra0.x,ra0.x,fmaf(ra0.y,ra0.y,fmaf(ra0.z,ra0.z,fmaf(ra0.w,ra0.w,nA0))));
            nA1 = fmaf(ra1.x,ra1.x,fmaf(ra1.y,ra1.y,fmaf(ra1.z,ra1.z,fmaf(ra1.w,ra1.w,nA1))));
#pragma unroll
            for (int i = 0; i < 4; i++)
                nB[i] = fmaf(rb[i].x,rb[i].x,fmaf(rb[i].y,rb[i].y,fmaf(rb[i].z,rb[i].z,fmaf(rb[i].w,rb[i].w,nB[i]))));
            __syncthreads();
        }
    }

    // reduce norms: each row's 8 k-chunk threads share t>>3 -> xor 1,2,4 in-warp
    nA0 += __shfl_xor_sync(0xffffffffu, nA0, 1);
    nA0 += __shfl_xor_sync(0xffffffffu, nA0, 2);
    nA0 += __shfl_xor_sync(0xffffffffu, nA0, 4);
    nA1 += __shfl_xor_sync(0xffffffffu, nA1, 1);
    nA1 += __shfl_xor_sync(0xffffffffu, nA1, 2);
    nA1 += __shfl_xor_sync(0xffffffffu, nA1, 4);
#pragma unroll
    for (int i = 0; i < 4; i++) {
        nB[i] += __shfl_xor_sync(0xffffffffu, nB[i], 1);
        nB[i] += __shfl_xor_sync(0xffffffffu, nB[i], 2);
        nB[i] += __shfl_xor_sync(0xffffffffu, nB[i], 4);
    }
    __syncthreads();
    if (ac4 == 0) {
        snA[arow]      = nA0;
        snA[arow + 16] = nA1;
#pragma unroll
        for (int i = 0; i < 4; i++) snB[arow + 16 * i] = nB[i];
    }
    __syncthreads();

    // epilogue: distances, diag = 1e6
#pragma unroll
    for (int i = 0; i < 4; i++) {
        const int q  = q0 + ty * 4 + i;
        const int mb = m0 + tx * 4;
        const float nq = snA[ty * 4 + i];
        float dv[4];
#pragma unroll
        for (int c = 0; c < 4; c++) {
            float d2 = nq + snB[tx * 4 + c] - 2.f * acc[i][c];
            dv[c] = (q == mb + c) ? 1e6f : sqrtf(fmaxf(d2, 1e-12f));
        }
        *(float4*)&g_D[(size_t)q * N + mb] = make_float4(dv[0], dv[1], dv[2], dv[3]);
    }
}

// ---------------- Kernel 2: soft precision (R8-proven, verbatim) ----------------
__global__ void __launch_bounds__(512) k_prec(const int* __restrict__ labels,
                                              float* __restrict__ out) {
    __shared__ float sd[4][N];
    __shared__ int   slab[N];
    __shared__ float wnum[16];
    __shared__ int   wcnt[16];
    __shared__ float swr[16];
    __shared__ int   s_done;

    const int t    = threadIdx.x;
    const int lane = t & 31;
    const int w    = t >> 5;
    const int q0   = blockIdx.x * 4;

    ((float4*)sd)[t] = __ldcg(&((const float4*)(g_D + (size_t)q0 * N))[t]);
    if (t < 128) ((int4*)slab)[t] = ((const int4*)labels)[t];
    __syncthreads();

    const int   qsel = w & 3;
    const int   q    = q0 + qsel;
    const int   lq   = slab[q];
    const float* row = sd[qsel];
    const int   jb   = (w >> 2) * 128;

    float num = 0.f;
    int   cnt = 0;
#pragma unroll
    for (int c = 0; c < 4; c++) {
        int j = jb + c * 32 + lane;
        bool f = (j != q) && (slab[j] == lq);
        unsigned bm = __ballot_sync(0xffffffffu, f);
        cnt += __popc(bm);
        while (bm) {                         // ascending j: deterministic
            int bit = __ffs(bm) - 1;
            bm &= bm - 1;
            float dj = row[jb + c * 32 + bit];
            float part = 0.f;
#pragma unroll
            for (int i = 0; i < 16; i++)
                part += sigmoid_nb((dj - row[lane + 32 * i]) * 100.0f); // 1/T2
#pragma unroll
            for (int o = 16; o; o >>= 1)
                part += __shfl_xor_sync(0xffffffffu, part, o);
            num += sigmoid_nb(5.0f - part);  // K=5, T1=1
        }
    }
    if (lane == 0) { wnum[w] = num; wcnt[w] = cnt; }
    __syncthreads();

    if (t < 4) {   // thread t finalizes query q0+t in fixed quarter order
        float s = wnum[t] + wnum[4 + t] + wnum[8 + t] + wnum[12 + t];
        int   c = wcnt[t] + wcnt[4 + t] + wcnt[8 + t] + wcnt[12 + t];
        g_prec[q0 + t] = s / fminf((float)c, 5.0f);  // 0/0 -> NaN like reference
    }
    __syncthreads();

    if (t == 0) {
        __threadfence();
        unsigned tk = atomicAdd(&g_ctr, 1u);
        s_done = ((tk & 127u) == 127u) ? 1 : 0;
    }
    __syncthreads();

    if (s_done) {    // last block: deterministic fixed-order mean
        __threadfence();
        float v = __ldcg(&g_prec[t]);        // 512 threads, 512 values
#pragma unroll
        for (int o = 16; o; o >>= 1)
            v += __shfl_xor_sync(0xffffffffu, v, o);
        if (lane == 0) swr[w] = v;
        __syncthreads();
        if (t == 0) {
            float s = 0.f;
#pragma unroll
            for (int i = 0; i < 16; i++) s += swr[i];
            out[0] = 1.0f - s / (float)N;
        }
    }
}

extern "C" void kernel_launch(void* const* d_in, const int* in_sizes, int n_in,
                              void* d_out, int out_size) {
    const float* emb    = (const float*)d_in[0];
    const int*   labels = (const int*)d_in[1];
    k_gram<<<128, 128>>>(emb);
    k_prec<<<128, 512>>>(labels, (float*)d_out);
}